// round 8
// baseline (speedup 1.0000x reference)
#include <cuda_runtime.h>
#include <cuda_bf16.h>

// Problem shapes (fixed by reference setup_inputs)
#define B    4
#define CIN  512
#define OUT  256
#define NN   4096

#define GRID 1024         // one block per output row; 2 input rows per block
#define TPB  256

// Scratch + per-batch sync state (zero-init; reset each run by last finisher)
__device__ float    g_X[B * CIN];
__device__ unsigned g_arrive[B];
__device__ unsigned g_done[B];

__global__ void __launch_bounds__(TPB, 5)
k_all(const float* __restrict__ x, const float* __restrict__ W1,
      float* __restrict__ out) {
    const int t    = threadIdx.x;
    const int warp = t >> 5;
    const int lane = t & 31;
    const int bo   = blockIdx.x;       // 0..1023
    const int b    = bo >> 8;          // batch; rows 2bo,2bo+1 are in batch b too
    const int o    = bo & 255;

    // ---------------- phase 1: reduce rows 2bo and 2bo+1 ----------------
    const float4* __restrict__ p0 =
        reinterpret_cast<const float4*>(x) + (size_t)(2 * bo + 0) * (NN / 4);
    const float4* __restrict__ p1 =
        reinterpret_cast<const float4*>(x) + (size_t)(2 * bo + 1) * (NN / 4);

    // 8 independent 128-bit loads in flight before any arithmetic
    float4 u0 = p0[t];       float4 u1 = p0[t + 256];
    float4 u2 = p0[t + 512]; float4 u3 = p0[t + 768];
    float4 w0 = p1[t];       float4 w1 = p1[t + 256];
    float4 w2 = p1[t + 512]; float4 w3 = p1[t + 768];

    float s0 = ((u0.x + u0.y) + (u0.z + u0.w)) + ((u1.x + u1.y) + (u1.z + u1.w))
             + ((u2.x + u2.y) + (u2.z + u2.w)) + ((u3.x + u3.y) + (u3.z + u3.w));
    float s1 = ((w0.x + w0.y) + (w0.z + w0.w)) + ((w1.x + w1.y) + (w1.z + w1.w))
             + ((w2.x + w2.y) + (w2.z + w2.w)) + ((w3.x + w3.y) + (w3.z + w3.w));

    #pragma unroll
    for (int off = 16; off > 0; off >>= 1) {
        s0 += __shfl_down_sync(0xffffffffu, s0, off);
        s1 += __shfl_down_sync(0xffffffffu, s1, off);
    }
    __shared__ float sm[2][8];
    if (lane == 0) { sm[0][warp] = s0; sm[1][warp] = s1; }
    __syncthreads();
    if (t < 2) {
        const float* r = sm[t];
        g_X[2 * bo + t] = ((r[0] + r[1]) + (r[2] + r[3]))
                        + ((r[4] + r[5]) + (r[6] + r[7]));
        __threadfence();                     // publish before arrival
    }
    __syncthreads();

    // ---------------- per-batch arrive + wait (t==0 spins) ----------------
    if (t == 0) {
        atomicAdd(&g_arrive[b], 1u);
        while (*(volatile unsigned*)&g_arrive[b] < 256u) { }
        __threadfence();                     // acquire g_X written by peers
    }
    __syncthreads();

    // ---------------- phase 2: dot + elu + broadcast (no more syncs) -------
    const float4* __restrict__ wr =
        reinterpret_cast<const float4*>(W1) + (size_t)o * (CIN / 4);
    const float4* __restrict__ xr =
        reinterpret_cast<const float4*>(g_X) + (size_t)b * (CIN / 4);

    float4 a0 = wr[lane];       float4 a1 = wr[lane + 32];
    float4 a2 = wr[lane + 64];  float4 a3 = wr[lane + 96];
    float4 b0 = __ldcg(xr + lane);       float4 b1 = __ldcg(xr + lane + 32);
    float4 b2 = __ldcg(xr + lane + 64);  float4 b3 = __ldcg(xr + lane + 96);

    float d0 = fmaf(a0.x, b0.x, fmaf(a0.y, b0.y, fmaf(a0.z, b0.z, a0.w * b0.w)));
    float d1 = fmaf(a1.x, b1.x, fmaf(a1.y, b1.y, fmaf(a1.z, b1.z, a1.w * b1.w)));
    float d2 = fmaf(a2.x, b2.x, fmaf(a2.y, b2.y, fmaf(a2.z, b2.z, a2.w * b2.w)));
    float d3 = fmaf(a3.x, b3.x, fmaf(a3.y, b3.y, fmaf(a3.z, b3.z, a3.w * b3.w)));
    float s  = (d0 + d1) + (d2 + d3);

    #pragma unroll
    for (int off = 16; off > 0; off >>= 1)   // butterfly: all lanes get sum
        s += __shfl_xor_sync(0xffffffffu, s, off);

    const float  e  = (s > 0.f) ? s : expm1f(s);   // elu, alpha=1
    const float4 v4 = make_float4(e, e, e, e);

    float4* __restrict__ q =
        reinterpret_cast<float4*>(out) + (size_t)bo * (NN / 4) + warp * 128;
    q[lane]      = v4;
    q[lane + 32] = v4;
    q[lane + 64] = v4;
    q[lane + 96] = v4;

    // ---------------- replay-safe counter reset ----------------
    // 256th done-incrementer can only exist after every spinner passed the
    // wait, so resetting g_arrive here cannot race this replay's waiters.
    if (t == 0) {
        const unsigned d = atomicAdd(&g_done[b], 1u);
        if (d == 255u) {
            g_arrive[b] = 0u;
            __threadfence();
            *(volatile unsigned*)&g_done[b] = 0u;
        }
    }
}

extern "C" void kernel_launch(void* const* d_in, const int* in_sizes, int n_in,
                              void* d_out, int out_size) {
    const float* x  = (const float*)d_in[0];   // [B, CIN, 1, NN]
    const float* W1 = (const float*)d_in[1];   // [OUT, CIN]
    // d_in[2] = w2, d_in[3] = bias_mat: unused (softmax over size-1 axis == 1)
    float* out = (float*)d_out;                // [B, OUT, 1, NN]

    k_all<<<GRID, TPB>>>(x, W1, out);
}

// round 9
// speedup vs baseline: 1.4775x; 1.4775x over previous
#include <cuda_runtime.h>
#include <cuda_bf16.h>

// Problem shapes (fixed by reference setup_inputs)
#define B    4
#define CIN  512
#define OUT  256
#define NN   4096

#define GRID 148          // one block per SM -> whole grid resident in wave 1
#define TPB  512          // 16 warps

// Scratch + barrier state (zero-init; sense-reversal is replay-safe)
__device__ float    g_X[B * CIN];
__device__ unsigned g_count = 0;
__device__ unsigned g_sense = 0;

__global__ void __launch_bounds__(TPB, 1)
k_all(const float* __restrict__ x, const float* __restrict__ W1,
      float* __restrict__ out) {
    const int t    = threadIdx.x;
    const int w    = t >> 5;           // 0..15
    const int lane = t & 31;
    const int blk  = blockIdx.x;       // 0..147

    // Capture sense before any work (no block can flip it until all arrive).
    const unsigned sense0 = *(volatile unsigned*)&g_sense;

    // ---------------- phase 1: one full input row per warp ----------------
    // row = w*148 + blk spreads active warps evenly across blocks.
    const int row = w * GRID + blk;          // 0..2367; 2048 active
    if (row < B * CIN) {
        const float4* __restrict__ p =
            reinterpret_cast<const float4*>(x) + (size_t)row * (NN / 4);
        float s = 0.f;
        #pragma unroll
        for (int g = 0; g < 4; g++) {        // 4 groups of 8 in-flight loads
            float4 v[8];
            #pragma unroll
            for (int i = 0; i < 8; i++) v[i] = p[lane + (g * 8 + i) * 32];
            #pragma unroll
            for (int i = 0; i < 8; i++)
                s += (v[i].x + v[i].y) + (v[i].z + v[i].w);
        }
        #pragma unroll
        for (int off = 16; off > 0; off >>= 1)
            s += __shfl_down_sync(0xffffffffu, s, off);
        if (lane == 0) g_X[row] = s;
    }
    __threadfence();                         // publish g_X before arrival
    __syncthreads();

    // ---------------- 148-way sense barrier with backoff ----------------
    if (t == 0) {
        const unsigned prev = atomicAdd(&g_count, 1u);
        if (prev == GRID - 1) {
            g_count = 0;                     // reset for next graph replay
            __threadfence();
            *(volatile unsigned*)&g_sense = sense0 ^ 1u;
        } else {
            while (*(volatile unsigned*)&g_sense == sense0)
                __nanosleep(64);             // keep pollers off the LTS
        }
        __threadfence();                     // acquire peers' g_X writes
    }
    __syncthreads();

    // ---------------- phase 2: one half output row per warp ----------------
    // 2048 half-row items on the same balanced mapping; 2 warps per row,
    // each redundantly computes the (L2-hot) 512-dot -> no intra-block sync.
    const int item = w * GRID + blk;         // 0..2367; 2048 active
    if (item < 2 * B * OUT) {
        const int ro   = item >> 1;          // output row 0..1023
        const int half = item & 1;
        const int b    = ro >> 8;            // OUT = 256
        const int o    = ro & 255;

        const float4* __restrict__ wr =
            reinterpret_cast<const float4*>(W1) + (size_t)o * (CIN / 4);
        const float4* __restrict__ xr =
            reinterpret_cast<const float4*>(g_X) + (size_t)b * (CIN / 4);

        float4 a0 = wr[lane];       float4 a1 = wr[lane + 32];
        float4 a2 = wr[lane + 64];  float4 a3 = wr[lane + 96];
        float4 b0 = __ldcg(xr + lane);       float4 b1 = __ldcg(xr + lane + 32);
        float4 b2 = __ldcg(xr + lane + 64);  float4 b3 = __ldcg(xr + lane + 96);

        float d0 = fmaf(a0.x, b0.x, fmaf(a0.y, b0.y, fmaf(a0.z, b0.z, a0.w * b0.w)));
        float d1 = fmaf(a1.x, b1.x, fmaf(a1.y, b1.y, fmaf(a1.z, b1.z, a1.w * b1.w)));
        float d2 = fmaf(a2.x, b2.x, fmaf(a2.y, b2.y, fmaf(a2.z, b2.z, a2.w * b2.w)));
        float d3 = fmaf(a3.x, b3.x, fmaf(a3.y, b3.y, fmaf(a3.z, b3.z, a3.w * b3.w)));
        float s  = (d0 + d1) + (d2 + d3);

        #pragma unroll
        for (int off = 16; off > 0; off >>= 1)   // butterfly: all lanes get sum
            s += __shfl_xor_sync(0xffffffffu, s, off);

        const float  e  = (s > 0.f) ? s : expm1f(s);   // elu, alpha=1
        const float4 v4 = make_float4(e, e, e, e);

        float4* __restrict__ q = reinterpret_cast<float4*>(out)
                               + (size_t)ro * (NN / 4) + half * 512;
        #pragma unroll
        for (int i = 0; i < 16; i++)             // 512 float4 / 32 lanes
            q[lane + i * 32] = v4;
    }
}

extern "C" void kernel_launch(void* const* d_in, const int* in_sizes, int n_in,
                              void* d_out, int out_size) {
    const float* x  = (const float*)d_in[0];   // [B, CIN, 1, NN]
    const float* W1 = (const float*)d_in[1];   // [OUT, CIN]
    // d_in[2] = w2, d_in[3] = bias_mat: unused (softmax over size-1 axis == 1)
    float* out = (float*)d_out;                // [B, OUT, 1, NN]

    k_all<<<GRID, TPB>>>(x, W1, out);
}